// round 1
// baseline (speedup 1.0000x reference)
#include <cuda_runtime.h>
#include <math.h>

#define NN 2048
#define TT 4096
#define MAX_SPIKES 256
#define ALPHA 0.01f
#define DT (1.0f/4096.0f)

// Output layout (floats), tuple order: ys, tevents, yevents, event_types, num_spikes
#define YS_LEN   ((size_t)TT * NN * 3)            // 25165824
#define TEV_OFF  (YS_LEN)                         // 25165824
#define YEV_OFF  (TEV_OFF + MAX_SPIKES)           // 25166080
#define YEV_LEN  ((size_t)MAX_SPIKES * NN * 3)    // 1572864
#define ET_OFF   (YEV_OFF + YEV_LEN)              // 26738944
#define ET_LEN   ((size_t)MAX_SPIKES * NN)        // 524288
#define NS_OFF   (ET_OFF + ET_LEN)                // 27263232

__global__ void init_tail_kernel(float* __restrict__ out) {
    const float INF = __int_as_float(0x7f800000);
    size_t total = (size_t)MAX_SPIKES + YEV_LEN + ET_LEN;
    size_t stride = (size_t)gridDim.x * blockDim.x;
    for (size_t i = (size_t)blockIdx.x * blockDim.x + threadIdx.x; i < total; i += stride) {
        out[TEV_OFF + i] = (i < (size_t)MAX_SPIKES + YEV_LEN) ? INF : 0.0f;
    }
}

__device__ __forceinline__ float softplus_f(float v) {
    // jnp.logaddexp(v, 0) = max(v,0) + log1p(exp(-|v|))  (libdevice expf/log1pf)
    return __fadd_rn(fmaxf(v, 0.0f), log1pf(expf(-fabsf(v))));
}

__global__ void __launch_bounds__(1024, 1)
snn_kernel(const float* __restrict__ w,
           const float* __restrict__ mu,
           const float* __restrict__ v0,
           const float* __restrict__ i0,
           const float* __restrict__ ic,
           const float* __restrict__ u_rs,
           const float* __restrict__ u_init,
           float* __restrict__ out) {
    __shared__ int eidx[3];
    const int tid = threadIdx.x;
    const int n0 = 2 * tid, n1 = n0 + 1;

    if (tid < 3) eidx[tid] = NN;

    const float mu1 = mu[0], mu2 = mu[1];
    float v_0 = v0[n0], v_1 = v0[n1];
    float ii0 = i0[n0], ii1 = i0[n1];
    float s_0 = __fsub_rn(logf(u_init[n0]), ALPHA);
    float s_1 = __fsub_rn(logf(u_init[n1]), ALPHA);
    int cnt = 0;

    float2 icv = *(const float2*)(ic + n0);
    float2 uv  = *(const float2*)(u_rs + n0);
    __syncthreads();

    for (int t = 0; t < TT; ++t) {
        // ---- deterministic update (match reference op order; no FMA contraction)
        float v1_0 = __fadd_rn(v_0, __fmul_rn(DT, __fmul_rn(mu1, __fsub_rn(__fadd_rn(ii0, icv.x), v_0))));
        float v1_1 = __fadd_rn(v_1, __fmul_rn(DT, __fmul_rn(mu1, __fsub_rn(__fadd_rn(ii1, icv.y), v_1))));
        float i1_0 = __fadd_rn(ii0, __fmul_rn(DT, __fmul_rn(-mu2, ii0)));
        float i1_1 = __fadd_rn(ii1, __fmul_rn(DT, __fmul_rn(-mu2, ii1)));
        float s1_0 = __fadd_rn(s_0, __fmul_rn(DT, softplus_f(v_0)));
        float s1_1 = __fadd_rn(s_1, __fmul_rn(DT, softplus_f(v_1)));

        bool m0 = (s1_0 >= 0.0f), m1 = (s1_1 >= 0.0f);

        // ---- single-barrier argmin reduction via 3 rotating buffers
        int b = t % 3;
        if (m0)      atomicMin(&eidx[b], n0);
        else if (m1) atomicMin(&eidx[b], n1);

        // ---- prefetch next ic/u rows (off the critical chain)
        float2 icn = make_float2(0.0f, 0.0f), un = make_float2(1.0f, 1.0f);
        if (t + 1 < TT) {
            icn = *(const float2*)(ic   + (size_t)(t + 1) * NN + n0);
            un  = *(const float2*)(u_rs + (size_t)(t + 1) * NN + n0);
        }

        __syncthreads();
        int e = eidx[b];
        if (tid == 0) eidx[(t + 2) % 3] = NN;   // reset buffer for step t+3 (safe: barrier-separated)

        bool event = (e < NN);
        float w0 = 0.0f, w1 = 0.0f;
        if (event) {
            float2 wr = *(const float2*)(w + (size_t)e * NN + n0);
            w0 = wr.x; w1 = wr.y;
        }

        // transition (equals [v1,i1,s1] when !event since mask all false and w=0)
        float v2_0 = __fsub_rn(v1_0, m0 ? 1.0f : 0.0f);
        float v2_1 = __fsub_rn(v1_1, m1 ? 1.0f : 0.0f);
        float i2_0 = __fadd_rn(i1_0, w0);
        float i2_1 = __fadd_rn(i1_1, w1);
        float s2_0 = m0 ? __fsub_rn(logf(uv.x), ALPHA) : s1_0;
        float s2_1 = m1 ? __fsub_rn(logf(uv.y), ALPHA) : s1_1;

        // ---- record event (first MAX_SPIKES event-steps)
        if (event && cnt < MAX_SPIKES) {
            if (tid == 0) out[TEV_OFF + cnt] = __fmul_rn((float)t + 1.0f, DT);
            float* ye = out + YEV_OFF + (size_t)cnt * (NN * 3) + 6 * (size_t)tid;
            *(float2*)(ye)     = make_float2(v1_0, i1_0);
            *(float2*)(ye + 2) = make_float2(s1_0, v1_1);
            *(float2*)(ye + 4) = make_float2(i1_1, s1_1);
            float* er = out + ET_OFF + (size_t)cnt * NN + n0;
            *(float2*)(er) = make_float2(m0 ? 1.0f : 0.0f, m1 ? 1.0f : 0.0f);
            cnt++;
        }

        // commit state
        v_0 = v2_0; v_1 = v2_1;
        ii0 = i2_0; ii1 = i2_1;
        s_0 = s2_0; s_1 = s2_1;

        // ---- stream ys[t] (y_new)
        float* yrow = out + (size_t)t * (NN * 3) + 6 * (size_t)tid;
        *(float2*)(yrow)     = make_float2(v_0, ii0);
        *(float2*)(yrow + 2) = make_float2(s_0, v_1);
        *(float2*)(yrow + 4) = make_float2(ii1, s_1);

        icv = icn; uv = un;
    }

    if (tid == 0) out[NS_OFF] = (float)cnt;
}

extern "C" void kernel_launch(void* const* d_in, const int* in_sizes, int n_in,
                              void* d_out, int out_size) {
    // metadata order: w, mu, v0, i0, ic, u_init, u_resample
    const float* w      = (const float*)d_in[0];
    const float* mu     = (const float*)d_in[1];
    const float* v0     = (const float*)d_in[2];
    const float* i0     = (const float*)d_in[3];
    const float* ic     = (const float*)d_in[4];
    const float* u_init = (const float*)d_in[5];
    const float* u_rs   = (const float*)d_in[6];
    float* out = (float*)d_out;

    init_tail_kernel<<<512, 256>>>(out);
    snn_kernel<<<1, 1024>>>(w, mu, v0, i0, ic, u_rs, u_init, out);
}